// round 1
// baseline (speedup 1.0000x reference)
#include <cuda_runtime.h>
#include <cuda_bf16.h>
#include <stdint.h>

// ---------------------------------------------------------------------------
// VectorQuantizer on GB300.
//   z      : [64, 256, 32, 32] f32   (d_in[0])
//   emb_w  : [1024, 256]       f32   (d_in[1])
//   out    : z_q [64,256,32,32] f32 followed by loss scalar (out_size-1 | last)
//
// Distances must be computed in fp32 with the reference formula shape
//   d = fl( fl(z_sq + e_sq[k]) - 2*dot_k )
// because the reference argmin is quantized at ULP(z_sq~256)=3e-5; monotone
// fp32 rounding of the same formula preserves its ordering. argmin ties break
// to the lowest index (jnp.argmin first-occurrence semantics).
// ---------------------------------------------------------------------------

#define BDIM   64
#define CDIM   256
#define HWDIM  1024
#define NROWS  65536          // BDIM * HWDIM
#define KCODES 1024

// scratch (device globals: no allocation allowed in kernel_launch)
__device__ float g_zT[(size_t)NROWS * CDIM];   // 64 MB: z transposed to [n][c]
__device__ float g_esq[KCODES];
__device__ float g_zsq[NROWS];
__device__ int   g_idx[NROWS];
__device__ float g_partials[2048];

// ---------------------------------------------------------------------------
// packed f32x2 FMA (Blackwell): 2 independent fp32 FMAs per instruction
// ---------------------------------------------------------------------------
__device__ __forceinline__ unsigned long long ffma2(unsigned long long a,
                                                    unsigned long long b,
                                                    unsigned long long c) {
    unsigned long long d;
    asm("fma.rn.f32x2 %0, %1, %2, %3;" : "=l"(d) : "l"(a), "l"(b), "l"(c));
    return d;
}
__device__ __forceinline__ float f32x2_sum(unsigned long long v) {
    float lo, hi;
    asm("mov.b64 {%0, %1}, %2;" : "=f"(lo), "=f"(hi) : "l"(v));
    return lo + hi;
}

// ---------------------------------------------------------------------------
// K0: transpose z [b][c][hw] -> zT [b*hw + hw_idx][c]
// ---------------------------------------------------------------------------
__global__ void k_transpose(const float* __restrict__ z) {
    __shared__ float tile[32][33];
    int b  = blockIdx.z;
    int c0 = blockIdx.y * 32;
    int h0 = blockIdx.x * 32;
    int tx = threadIdx.x, ty = threadIdx.y;   // 32 x 8
#pragma unroll
    for (int i = 0; i < 32; i += 8)
        tile[ty + i][tx] = z[(((size_t)(b * CDIM + c0 + ty + i)) << 10) + h0 + tx];
    __syncthreads();
#pragma unroll
    for (int i = 0; i < 32; i += 8)
        g_zT[(size_t)(b * HWDIM + h0 + ty + i) * CDIM + c0 + tx] = tile[tx][ty + i];
}

// ---------------------------------------------------------------------------
// K1: per-row squared norms (warp per row, fixed deterministic order)
// ---------------------------------------------------------------------------
__global__ void k_esq(const float* __restrict__ emb) {
    int w    = (blockIdx.x * blockDim.x + threadIdx.x) >> 5;
    int lane = threadIdx.x & 31;
    if (w >= KCODES) return;
    const float* row = emb + (size_t)w * CDIM;
    float s = 0.f;
#pragma unroll
    for (int i = lane; i < CDIM; i += 32) { float v = row[i]; s = fmaf(v, v, s); }
#pragma unroll
    for (int o = 16; o; o >>= 1) s += __shfl_xor_sync(0xffffffffu, s, o);
    if (!lane) g_esq[w] = s;
}

__global__ void k_zsq() {
    int w    = (blockIdx.x * blockDim.x + threadIdx.x) >> 5;
    int lane = threadIdx.x & 31;
    if (w >= NROWS) return;
    const float* row = g_zT + (size_t)w * CDIM;
    float s = 0.f;
#pragma unroll
    for (int i = lane; i < CDIM; i += 32) { float v = row[i]; s = fmaf(v, v, s); }
#pragma unroll
    for (int o = 16; o; o >>= 1) s += __shfl_xor_sync(0xffffffffu, s, o);
    if (!lane) g_zsq[w] = s;
}

// ---------------------------------------------------------------------------
// K2: fused distance GEMM + argmin.
//   block: 128 rows x all 1024 codes (code tiles of 128, c chunks of 32)
//   thread: 8 rows x 8 codes, f32x2 accumulators over (even,odd) c partials
// ---------------------------------------------------------------------------
#define BR  128
#define BKT 128
#define BC  32

__global__ void __launch_bounds__(256, 1)
k_dist_argmin(const float* __restrict__ emb) {
    __shared__ union {
        struct { float zs[BR][BC + 4]; float es[BKT][BC + 4]; } a;
        struct { float d[BR][16]; int i[BR][16]; } b;
    } sm;

    const int t    = threadIdx.x;
    const int tx   = t & 15;        // code group (8 codes)
    const int ty   = t >> 4;        // row group (8 rows)
    const int row0 = blockIdx.x * BR;

    float bestD[8];
    int   bestI[8];
#pragma unroll
    for (int i = 0; i < 8; ++i) { bestD[i] = __int_as_float(0x7f800000); bestI[i] = 0; }

    float zq8[8];
#pragma unroll
    for (int i = 0; i < 8; ++i) zq8[i] = g_zsq[row0 + ty * 8 + i];

    for (int k0 = 0; k0 < KCODES; k0 += BKT) {
        unsigned long long acc[8][8];
#pragma unroll
        for (int i = 0; i < 8; ++i)
#pragma unroll
            for (int j = 0; j < 8; ++j) acc[i][j] = 0ull;

        float e8[8];
#pragma unroll
        for (int j = 0; j < 8; ++j) e8[j] = g_esq[k0 + tx * 8 + j];

        for (int c0 = 0; c0 < CDIM; c0 += BC) {
            __syncthreads();
            // stage 128x32 z tile and 128x32 emb tile (float4, coalesced)
#pragma unroll
            for (int i = 0; i < 4; ++i) {
                int q  = t + 256 * i;
                int r  = q >> 3;
                int cs = (q & 7) * 4;
                float4 v = *reinterpret_cast<const float4*>(
                    &g_zT[(size_t)(row0 + r) * CDIM + c0 + cs]);
                *reinterpret_cast<float4*>(&sm.a.zs[r][cs]) = v;
                float4 w = *reinterpret_cast<const float4*>(
                    &emb[(size_t)(k0 + r) * CDIM + c0 + cs]);
                *reinterpret_cast<float4*>(&sm.a.es[r][cs]) = w;
            }
            __syncthreads();

#pragma unroll
            for (int cc = 0; cc < BC; cc += 2) {
                unsigned long long zf[8], ef[8];
#pragma unroll
                for (int i = 0; i < 8; ++i)
                    zf[i] = *reinterpret_cast<const unsigned long long*>(
                        &sm.a.zs[ty * 8 + i][cc]);
#pragma unroll
                for (int j = 0; j < 8; ++j)
                    ef[j] = *reinterpret_cast<const unsigned long long*>(
                        &sm.a.es[tx * 8 + j][cc]);
#pragma unroll
                for (int i = 0; i < 8; ++i)
#pragma unroll
                    for (int j = 0; j < 8; ++j)
                        acc[i][j] = ffma2(zf[i], ef[j], acc[i][j]);
            }
        }

        // tile epilogue: distances + running argmin (codes ascending -> first-min)
#pragma unroll
        for (int i = 0; i < 8; ++i) {
#pragma unroll
            for (int j = 0; j < 8; ++j) {
                float dot = f32x2_sum(acc[i][j]);
                float t1  = zq8[i] + e8[j];              // fl(zsq + esq)
                float d   = fmaf(-2.0f, dot, t1);        // fl(t1 - 2*dot)
                int   k   = k0 + tx * 8 + j;
                if (d < bestD[i]) { bestD[i] = d; bestI[i] = k; }
            }
        }
    }

    // cross-thread (tx) reduction per row, lowest-index tie-break
    __syncthreads();
#pragma unroll
    for (int i = 0; i < 8; ++i) {
        sm.b.d[ty * 8 + i][tx] = bestD[i];
        sm.b.i[ty * 8 + i][tx] = bestI[i];
    }
    __syncthreads();
    if (t < BR) {
        float bd = sm.b.d[t][0];
        int   bi = sm.b.i[t][0];
#pragma unroll
        for (int x = 1; x < 16; ++x) {
            float dd = sm.b.d[t][x];
            int   ii = sm.b.i[t][x];
            if (dd < bd || (dd == bd && ii < bi)) { bd = dd; bi = ii; }
        }
        g_idx[row0 + t] = bi;
    }
}

// ---------------------------------------------------------------------------
// K3: gather z_q -> out ([B,C,H,W] layout), per-block loss partial sums
// ---------------------------------------------------------------------------
__global__ void __launch_bounds__(256)
k_output(const float* __restrict__ z, const float* __restrict__ emb,
         float* __restrict__ out) {
    __shared__ float es[32][257];
    __shared__ int   sid[32];
    __shared__ float red[256];

    const int t  = threadIdx.x;
    const int n0 = blockIdx.x * 32;
    if (t < 32) sid[t] = g_idx[n0 + t];
    __syncthreads();

    const int w = t >> 5, lane = t & 31;
#pragma unroll
    for (int r = w * 4; r < w * 4 + 4; ++r) {
        const float* src = emb + (size_t)sid[r] * CDIM;
#pragma unroll
        for (int i = 0; i < CDIM; i += 32) es[r][i + lane] = src[i + lane];
    }
    __syncthreads();

    const int b = n0 >> 10, hwb = n0 & 1023;
    float acc = 0.f;
#pragma unroll 4
    for (int p = 0; p < 32; ++p) {
        int c = p * 8 + (t >> 5);
        int r = t & 31;
        size_t g = (((size_t)(b * CDIM + c)) << 10) + hwb + r;
        float v  = es[r][c];
        float zv = z[g];
        out[g] = v;
        float df = v - zv;
        acc = fmaf(df, df, acc);
    }
    red[t] = acc;
    __syncthreads();
#pragma unroll
    for (int s = 128; s; s >>= 1) {
        if (t < s) red[t] += red[t + s];
        __syncthreads();
    }
    if (!t) g_partials[blockIdx.x] = red[0];
}

// ---------------------------------------------------------------------------
// K4: deterministic final loss = (1 + 0.25) * mean((z_q - z)^2)
// ---------------------------------------------------------------------------
__global__ void k_loss(float* __restrict__ lossOut) {
    __shared__ float red[256];
    const int t = threadIdx.x;
    float s = 0.f;
    for (int i = t; i < 2048; i += 256) s += g_partials[i];
    red[t] = s;
    __syncthreads();
#pragma unroll
    for (int st = 128; st; st >>= 1) {
        if (t < st) red[t] += red[t + st];
        __syncthreads();
    }
    if (!t) {
        float m = red[0] * (1.0f / 16777216.0f);
        lossOut[0] = m + 0.25f * m;   // embedding_loss + BETA*commitment_loss
    }
}

// ---------------------------------------------------------------------------
extern "C" void kernel_launch(void* const* d_in, const int* in_sizes, int n_in,
                              void* d_out, int out_size) {
    const float* z   = (const float*)d_in[0];
    const float* emb = (const float*)d_in[1];
    float* out       = (float*)d_out;

    k_transpose<<<dim3(32, 8, 64), dim3(32, 8)>>>(z);
    k_esq<<<(KCODES * 32) / 256, 256>>>(emb);
    k_zsq<<<(NROWS * 32) / 256, 256>>>();
    k_dist_argmin<<<NROWS / BR, 256>>>(emb);
    k_output<<<NROWS / 32, 256>>>(z, emb, out);
    k_loss<<<1, 256>>>(out + (size_t)out_size - 1);
}

// round 2
// speedup vs baseline: 2.7185x; 2.7185x over previous
#include <cuda_runtime.h>
#include <cuda_bf16.h>
#include <stdint.h>

// ---------------------------------------------------------------------------
// VectorQuantizer on GB300.
//   z      : [64, 256, 32, 32] f32   (d_in[0])
//   emb_w  : [1024, 256]       f32   (d_in[1])
//   out    : z_q [64,256,32,32] f32 followed by loss scalar (last element)
//
// Distances in fp32 with the reference formula shape
//   d = fl( fl(z_sq + e_sq[k]) - 2*dot_k )
// (monotone rounding of the same formula preserves the reference argmin
//  ordering). argmin ties break to the lowest code index.
// ---------------------------------------------------------------------------

#define BDIM   64
#define CDIM   256
#define HWDIM  1024
#define NROWS  65536          // BDIM * HWDIM
#define KCODES 1024

// scratch (device globals: no allocation allowed in kernel_launch)
__device__ float g_zT[(size_t)NROWS * CDIM];   // 64 MB: z transposed to [n][c]
__device__ float g_esq[KCODES];
__device__ float g_zsq[NROWS];
__device__ int   g_idx[NROWS];
__device__ float g_partials[2048];

// ---------------------------------------------------------------------------
// packed f32x2 FMA (Blackwell): 2 independent fp32 FMAs per instruction
// ---------------------------------------------------------------------------
__device__ __forceinline__ unsigned long long ffma2(unsigned long long a,
                                                    unsigned long long b,
                                                    unsigned long long c) {
    unsigned long long d;
    asm("fma.rn.f32x2 %0, %1, %2, %3;" : "=l"(d) : "l"(a), "l"(b), "l"(c));
    return d;
}
__device__ __forceinline__ float f32x2_sum(unsigned long long v) {
    float lo, hi;
    asm("mov.b64 {%0, %1}, %2;" : "=f"(lo), "=f"(hi) : "l"(v));
    return lo + hi;
}

// ---------------------------------------------------------------------------
// K0: transpose z [b][c][hw] -> zT [b*hw + hw_idx][c]
// ---------------------------------------------------------------------------
__global__ void k_transpose(const float* __restrict__ z) {
    __shared__ float tile[32][33];
    int b  = blockIdx.z;
    int c0 = blockIdx.y * 32;
    int h0 = blockIdx.x * 32;
    int tx = threadIdx.x, ty = threadIdx.y;   // 32 x 8
#pragma unroll
    for (int i = 0; i < 32; i += 8)
        tile[ty + i][tx] = z[(((size_t)(b * CDIM + c0 + ty + i)) << 10) + h0 + tx];
    __syncthreads();
#pragma unroll
    for (int i = 0; i < 32; i += 8)
        g_zT[(size_t)(b * HWDIM + h0 + ty + i) * CDIM + c0 + tx] = tile[tx][ty + i];
}

// ---------------------------------------------------------------------------
// K1: per-row squared norms (warp per row, fixed deterministic order)
// ---------------------------------------------------------------------------
__global__ void k_esq(const float* __restrict__ emb) {
    int w    = (blockIdx.x * blockDim.x + threadIdx.x) >> 5;
    int lane = threadIdx.x & 31;
    if (w >= KCODES) return;
    const float* row = emb + (size_t)w * CDIM;
    float s = 0.f;
#pragma unroll
    for (int i = lane; i < CDIM; i += 32) { float v = row[i]; s = fmaf(v, v, s); }
#pragma unroll
    for (int o = 16; o; o >>= 1) s += __shfl_xor_sync(0xffffffffu, s, o);
    if (!lane) g_esq[w] = s;
}

__global__ void k_zsq() {
    int w    = (blockIdx.x * blockDim.x + threadIdx.x) >> 5;
    int lane = threadIdx.x & 31;
    if (w >= NROWS) return;
    const float* row = g_zT + (size_t)w * CDIM;
    float s = 0.f;
#pragma unroll
    for (int i = lane; i < CDIM; i += 32) { float v = row[i]; s = fmaf(v, v, s); }
#pragma unroll
    for (int o = 16; o; o >>= 1) s += __shfl_xor_sync(0xffffffffu, s, o);
    if (!lane) g_zsq[w] = s;
}

// ---------------------------------------------------------------------------
// K2: fused distance GEMM + argmin.
//   block: 128 rows x all 1024 codes (code tiles of 128, c chunks of 32)
//   thread: 8 rows (ty*8+i) x 8 codes (j*16+tx), f32x2 accs over (c,c+1)
//
// smem geometry (bank-conflict-free, derived for warp = {tx 0..15} x {2 ty}):
//   zs: row stride 34 floats. zf addr bank = (2r + cc) mod 32; warp rows
//       r, r+8 differ by 16 banks; 2 distinct broadcast addrs -> 1 phase.
//   es: row stride 32, column ROTATED by 2*(r&15). With code rows
//       r = j*16+tx, rotation = 2*tx, so ef bank = (cc + 2*tx) mod 32:
//       16 distinct even banks across tx, identical addrs across ty
//       (broadcast) -> 1 phase per LDS.64.
// ---------------------------------------------------------------------------
#define BR  128
#define BKT 128
#define BC  32
#define ZS_STRIDE 34

__global__ void __launch_bounds__(256, 1)
k_dist_argmin(const float* __restrict__ emb) {
    __shared__ union {
        struct { float zs[BR * ZS_STRIDE]; float es[BKT * BC]; } a;
        struct { float d[BR][16]; int i[BR][16]; } b;
    } sm;

    const int t    = threadIdx.x;
    const int tx   = t & 15;        // code lane (codes j*16+tx)
    const int ty   = t >> 4;        // row group (8 rows)
    const int row0 = blockIdx.x * BR;

    float bestD[8];
    int   bestI[8];
#pragma unroll
    for (int i = 0; i < 8; ++i) { bestD[i] = __int_as_float(0x7f800000); bestI[i] = 0; }

    float zq8[8];
#pragma unroll
    for (int i = 0; i < 8; ++i) zq8[i] = g_zsq[row0 + ty * 8 + i];

    // staging decomposition: 2048 float2 per tile, 8 per thread
    const int sr = t >> 4;          // base row  (0..15), +16 per step
    const int sc = (t & 15) * 2;    // base col  (0,2,...,30)

    for (int k0 = 0; k0 < KCODES; k0 += BKT) {
        unsigned long long acc[8][8];
#pragma unroll
        for (int i = 0; i < 8; ++i)
#pragma unroll
            for (int j = 0; j < 8; ++j) acc[i][j] = 0ull;

        float e8[8];
#pragma unroll
        for (int j = 0; j < 8; ++j) e8[j] = g_esq[k0 + j * 16 + tx];

        for (int c0 = 0; c0 < CDIM; c0 += BC) {
            __syncthreads();
            // stage 128x32 z tile (stride 34) and 128x32 emb tile (rotated)
#pragma unroll
            for (int s = 0; s < 8; ++s) {
                int r = sr + s * 16;
                float2 v = *reinterpret_cast<const float2*>(
                    &g_zT[(size_t)(row0 + r) * CDIM + c0 + sc]);
                *reinterpret_cast<float2*>(&sm.a.zs[r * ZS_STRIDE + sc]) = v;
                float2 w = *reinterpret_cast<const float2*>(
                    &emb[(size_t)(k0 + r) * CDIM + c0 + sc]);
                int pos = (sc + 2 * (r & 15)) & 31;
                *reinterpret_cast<float2*>(&sm.a.es[r * BC + pos]) = w;
            }
            __syncthreads();

#pragma unroll
            for (int cc = 0; cc < BC; cc += 2) {
                const int pos = (cc + 2 * tx) & 31;   // es rotation for r&15==tx
                unsigned long long zf[8], ef[8];
#pragma unroll
                for (int i = 0; i < 8; ++i)
                    zf[i] = *reinterpret_cast<const unsigned long long*>(
                        &sm.a.zs[(ty * 8 + i) * ZS_STRIDE + cc]);
#pragma unroll
                for (int j = 0; j < 8; ++j)
                    ef[j] = *reinterpret_cast<const unsigned long long*>(
                        &sm.a.es[(j * 16 + tx) * BC + pos]);
#pragma unroll
                for (int i = 0; i < 8; ++i)
#pragma unroll
                    for (int j = 0; j < 8; ++j)
                        acc[i][j] = ffma2(zf[i], ef[j], acc[i][j]);
            }
        }

        // tile epilogue: distances + running argmin
        // (within-thread code indices ascend with j; strict < keeps first-min)
#pragma unroll
        for (int i = 0; i < 8; ++i) {
#pragma unroll
            for (int j = 0; j < 8; ++j) {
                float dot = f32x2_sum(acc[i][j]);
                float t1  = zq8[i] + e8[j];              // fl(zsq + esq)
                float d   = fmaf(-2.0f, dot, t1);        // fl(t1 - 2*dot)
                int   k   = k0 + j * 16 + tx;
                if (d < bestD[i]) { bestD[i] = d; bestI[i] = k; }
            }
        }
    }

    // cross-thread (tx) reduction per row, lowest-index tie-break
    __syncthreads();
#pragma unroll
    for (int i = 0; i < 8; ++i) {
        sm.b.d[ty * 8 + i][tx] = bestD[i];
        sm.b.i[ty * 8 + i][tx] = bestI[i];
    }
    __syncthreads();
    if (t < BR) {
        float bd = sm.b.d[t][0];
        int   bi = sm.b.i[t][0];
#pragma unroll
        for (int x = 1; x < 16; ++x) {
            float dd = sm.b.d[t][x];
            int   ii = sm.b.i[t][x];
            if (dd < bd || (dd == bd && ii < bi)) { bd = dd; bi = ii; }
        }
        g_idx[row0 + t] = bi;
    }
}

// ---------------------------------------------------------------------------
// K3: gather z_q -> out ([B,C,H,W] layout), per-block loss partial sums
// ---------------------------------------------------------------------------
__global__ void __launch_bounds__(256)
k_output(const float* __restrict__ z, const float* __restrict__ emb,
         float* __restrict__ out) {
    __shared__ float es[32][257];
    __shared__ int   sid[32];
    __shared__ float red[256];

    const int t  = threadIdx.x;
    const int n0 = blockIdx.x * 32;
    if (t < 32) sid[t] = g_idx[n0 + t];
    __syncthreads();

    const int w = t >> 5, lane = t & 31;
#pragma unroll
    for (int r = w * 4; r < w * 4 + 4; ++r) {
        const float* src = emb + (size_t)sid[r] * CDIM;
#pragma unroll
        for (int i = 0; i < CDIM; i += 32) es[r][i + lane] = src[i + lane];
    }
    __syncthreads();

    const int b = n0 >> 10, hwb = n0 & 1023;
    float acc = 0.f;
#pragma unroll 4
    for (int p = 0; p < 32; ++p) {
        int c = p * 8 + (t >> 5);
        int r = t & 31;
        size_t g = (((size_t)(b * CDIM + c)) << 10) + hwb + r;
        float v  = es[r][c];
        float zv = z[g];
        out[g] = v;
        float df = v - zv;
        acc = fmaf(df, df, acc);
    }
    red[t] = acc;
    __syncthreads();
#pragma unroll
    for (int s = 128; s; s >>= 1) {
        if (t < s) red[t] += red[t + s];
        __syncthreads();
    }
    if (!t) g_partials[blockIdx.x] = red[0];
}

// ---------------------------------------------------------------------------
// K4: deterministic final loss = (1 + 0.25) * mean((z_q - z)^2)
// ---------------------------------------------------------------------------
__global__ void k_loss(float* __restrict__ lossOut) {
    __shared__ float red[256];
    const int t = threadIdx.x;
    float s = 0.f;
    for (int i = t; i < 2048; i += 256) s += g_partials[i];
    red[t] = s;
    __syncthreads();
#pragma unroll
    for (int st = 128; st; st >>= 1) {
        if (t < st) red[t] += red[t + st];
        __syncthreads();
    }
    if (!t) {
        float m = red[0] * (1.0f / 16777216.0f);
        lossOut[0] = m + 0.25f * m;   // embedding_loss + BETA*commitment_loss
    }
}

// ---------------------------------------------------------------------------
extern "C" void kernel_launch(void* const* d_in, const int* in_sizes, int n_in,
                              void* d_out, int out_size) {
    const float* z   = (const float*)d_in[0];
    const float* emb = (const float*)d_in[1];
    float* out       = (float*)d_out;

    k_transpose<<<dim3(32, 8, 64), dim3(32, 8)>>>(z);
    k_esq<<<(KCODES * 32) / 256, 256>>>(emb);
    k_zsq<<<(NROWS * 32) / 256, 256>>>();
    k_dist_argmin<<<NROWS / BR, 256>>>(emb);
    k_output<<<NROWS / 32, 256>>>(z, emb, out);
    k_loss<<<1, 256>>>(out + (size_t)out_size - 1);
}

// round 4
// speedup vs baseline: 2.8647x; 1.0538x over previous
#include <cuda_runtime.h>
#include <cuda_bf16.h>
#include <stdint.h>

// ---------------------------------------------------------------------------
// VectorQuantizer on GB300 — exact fp32 FFMA2 distance GEMM, occupancy-2.
//   z      : [64, 256, 32, 32] f32   (d_in[0])
//   emb_w  : [1024, 256]       f32   (d_in[1])
//   out    : z_q [64,256,32,32] f32, then loss scalar (last element)
//
// d = fl( fl(z_sq + e_sq[k]) - 2*dot_k ), fp32 throughout; argmin ties break
// to the lowest code index. Fully deterministic.
// ---------------------------------------------------------------------------

#define CDIM   256
#define NROWS  65536
#define KCODES 1024

__device__ float              g_esq[KCODES];
__device__ float              g_zsq[NROWS];
__device__ int                g_idx[NROWS];
__device__ float              g_partials[2048];
// e packed per (ktile of 128 codes, c-chunk of 32): [cc][code&127] floats,
// i.e. u64 pair (e[2q][c], e[2q+1][c]) at u64 index tile*2048 + cc*64 + q.
__device__ unsigned long long g_epack[131072];   // 1 MB

// ---------------------------------------------------------------------------
__device__ __forceinline__ unsigned long long ffma2(unsigned long long a,
                                                    unsigned long long b,
                                                    unsigned long long c) {
    unsigned long long d;
    asm("fma.rn.f32x2 %0, %1, %2, %3;" : "=l"(d) : "l"(a), "l"(b), "l"(c));
    return d;
}
__device__ __forceinline__ unsigned long long dup2(float z) {
    unsigned long long d;
    asm("mov.b64 %0, {%1, %1};" : "=l"(d) : "f"(z));
    return d;
}
__device__ __forceinline__ void unpack2(unsigned long long v, float& lo, float& hi) {
    asm("mov.b64 {%0, %1}, %2;" : "=f"(lo), "=f"(hi) : "l"(v));
}

// ---------------------------------------------------------------------------
// K0: pack emb into pair-interleaved GEMM tiles (runs once per call, 1 MB)
// ---------------------------------------------------------------------------
__global__ void k_epack(const float* __restrict__ emb) {
    int idx = blockIdx.x * 256 + threadIdx.x;     // 262144
    int k = idx & 1023, c = idx >> 10;
    int fidx = (((k >> 7) * 8 + (c >> 5)) * 32 + (c & 31)) * 128 + (k & 127);
    ((float*)g_epack)[fidx] = emb[k * CDIM + c];
}

// ---------------------------------------------------------------------------
// K1: norms
// ---------------------------------------------------------------------------
__global__ void k_esq(const float* __restrict__ emb) {
    int w = (blockIdx.x * blockDim.x + threadIdx.x) >> 5, lane = threadIdx.x & 31;
    if (w >= KCODES) return;
    const float* row = emb + (size_t)w * CDIM;
    float s = 0.f;
#pragma unroll
    for (int i = lane; i < CDIM; i += 32) { float v = row[i]; s = fmaf(v, v, s); }
#pragma unroll
    for (int o = 16; o; o >>= 1) s += __shfl_xor_sync(0xffffffffu, s, o);
    if (!lane) g_esq[w] = s;
}

// z_sq straight from the [b][c][hw] layout (coalesced across threads)
__global__ void k_zsq(const float* __restrict__ z) {
    int n = blockIdx.x * 256 + threadIdx.x;
    int b = n >> 10, hw = n & 1023;
    const float* p = z + (((size_t)b * CDIM) << 10) + hw;
    float s = 0.f;
#pragma unroll 8
    for (int c = 0; c < CDIM; c++) { float v = p[(size_t)c << 10]; s = fmaf(v, v, s); }
    g_zsq[n] = s;
}

// ---------------------------------------------------------------------------
// K2: fused distance GEMM + argmin, occupancy 2 blocks/SM.
//   block: 128 rows x 1024 codes (8 code-tiles of 128); c chunks of 32, step 1.
//   thread (tx=t&15, ty=t>>4): rows ty*8+i (i<8), codes kb+8tx+2p+h (p<4,h<2).
//   acc[i][p] is f32x2 over the code pair — each half a full dot product.
//   zsT[c][row] staged straight from z (no transpose pass); zf = 2x LDS.128,
//   (z,z) built on the ALU pipe. ef = 2x LDS.128 from pre-packed e tiles.
// ---------------------------------------------------------------------------
__global__ void __launch_bounds__(256, 2)
k_dist_argmin(const float* __restrict__ z) {
    __shared__ __align__(16) union {
        struct { float zsT[32 * 132]; unsigned long long es[2048]; } a;
        struct { float d[128][16]; int i[128][16]; } b;
    } sm;
    __shared__ float s_esq[KCODES];
    __shared__ float s_zsq[128];

    const int t    = threadIdx.x;
    const int tx   = t & 15;
    const int ty   = t >> 4;
    const int row0 = blockIdx.x * 128;
    const int bb   = row0 >> 10;        // batch index (128 rows within one b)
    const int hw0  = row0 & 1023;

    for (int i = t; i < KCODES; i += 256) s_esq[i] = g_esq[i];
    if (t < 128) s_zsq[t] = g_zsq[row0 + t];

    float bestD[8];
    int   bestI[8];
#pragma unroll
    for (int i = 0; i < 8; ++i) { bestD[i] = __int_as_float(0x7f800000); bestI[i] = 0; }

    // staging coords
    const int zr = t >> 3;              // c-row 0..31
    const int zf4 = (t & 7) * 4;        // float offset within 128-row span

    for (int kt = 0; kt < 8; kt++) {
        unsigned long long acc[8][4];
#pragma unroll
        for (int i = 0; i < 8; ++i)
#pragma unroll
            for (int p = 0; p < 4; ++p) acc[i][p] = 0ull;

        for (int c0 = 0; c0 < 8; c0++) {
            __syncthreads();
            // stage zsT[32 c][128 rows] (stride 132) from z, coalesced
            {
                const float* src = z + (((size_t)(bb * CDIM + c0 * 32 + zr)) << 10)
                                     + hw0 + zf4;
                float* dst = &sm.a.zsT[zr * 132 + zf4];
#pragma unroll
                for (int s = 0; s < 4; s++)
                    *reinterpret_cast<float4*>(dst + 32 * s) =
                        *reinterpret_cast<const float4*>(src + 32 * s);
            }
            // stage es tile (16KB memcpy from packed e)
            {
                const unsigned long long* src =
                    g_epack + ((size_t)(kt * 8 + c0)) * 2048 + t;
#pragma unroll
                for (int s = 0; s < 8; s++) sm.a.es[t + 256 * s] = src[256 * s];
            }
            __syncthreads();

#pragma unroll 2
            for (int cc = 0; cc < 32; cc++) {
                float4 za = *reinterpret_cast<const float4*>(
                    &sm.a.zsT[cc * 132 + ty * 8]);
                float4 zb = *reinterpret_cast<const float4*>(
                    &sm.a.zsT[cc * 132 + ty * 8 + 4]);
                ulonglong2 ea = *reinterpret_cast<const ulonglong2*>(
                    &sm.a.es[cc * 64 + tx * 4]);
                ulonglong2 eb = *reinterpret_cast<const ulonglong2*>(
                    &sm.a.es[cc * 64 + tx * 4 + 2]);
                float zv[8] = { za.x, za.y, za.z, za.w, zb.x, zb.y, zb.z, zb.w };
#pragma unroll
                for (int i = 0; i < 8; i++) {
                    unsigned long long zz = dup2(zv[i]);
                    acc[i][0] = ffma2(zz, ea.x, acc[i][0]);
                    acc[i][1] = ffma2(zz, ea.y, acc[i][1]);
                    acc[i][2] = ffma2(zz, eb.x, acc[i][2]);
                    acc[i][3] = ffma2(zz, eb.y, acc[i][3]);
                }
            }
        }

        // tile epilogue: per-thread codes ascend (p,h); strict < = first-min
        const int kb = kt * 128;
#pragma unroll
        for (int i = 0; i < 8; i++) {
            float zq = s_zsq[ty * 8 + i];
#pragma unroll
            for (int p = 0; p < 4; p++) {
                float lo, hi;
                unpack2(acc[i][p], lo, hi);
                int k0 = kb + tx * 8 + p * 2;
                float d0 = fmaf(-2.0f, lo, zq + s_esq[k0]);
                if (d0 < bestD[i]) { bestD[i] = d0; bestI[i] = k0; }
                float d1 = fmaf(-2.0f, hi, zq + s_esq[k0 + 1]);
                if (d1 < bestD[i]) { bestD[i] = d1; bestI[i] = k0 + 1; }
            }
        }
    }

    // cross-thread (tx) reduction per row, lowest-index tie-break
    __syncthreads();
#pragma unroll
    for (int i = 0; i < 8; ++i) {
        sm.b.d[ty * 8 + i][tx] = bestD[i];
        sm.b.i[ty * 8 + i][tx] = bestI[i];
    }
    __syncthreads();
    if (t < 128) {
        float bd = sm.b.d[t][0];
        int   bi = sm.b.i[t][0];
#pragma unroll
        for (int x = 1; x < 16; ++x) {
            float dd = sm.b.d[t][x];
            int   ii = sm.b.i[t][x];
            if (dd < bd || (dd == bd && ii < bi)) { bd = dd; bi = ii; }
        }
        g_idx[row0 + t] = bi;
    }
}

// ---------------------------------------------------------------------------
// K3: gather z_q -> out ([B,C,H,W]), per-block loss partials
// ---------------------------------------------------------------------------
__global__ void __launch_bounds__(256)
k_output(const float* __restrict__ z, const float* __restrict__ emb,
         float* __restrict__ out) {
    __shared__ float es[32][257];
    __shared__ int   sid[32];
    __shared__ float red[256];

    const int t  = threadIdx.x;
    const int n0 = blockIdx.x * 32;
    if (t < 32) sid[t] = g_idx[n0 + t];
    __syncthreads();

    const int w = t >> 5, lane = t & 31;
#pragma unroll
    for (int r = w * 4; r < w * 4 + 4; ++r) {
        const float* src = emb + (size_t)sid[r] * CDIM;
#pragma unroll
        for (int i = 0; i < CDIM; i += 32) es[r][i + lane] = src[i + lane];
    }
    __syncthreads();

    const int b = n0 >> 10, hwb = n0 & 1023;
    float acc = 0.f;
#pragma unroll 4
    for (int p = 0; p < 32; ++p) {
        int c = p * 8 + (t >> 5);
        int r = t & 31;
        size_t g = (((size_t)(b * CDIM + c)) << 10) + hwb + r;
        float v  = es[r][c];
        float zv = z[g];
        out[g] = v;
        float df = v - zv;
        acc = fmaf(df, df, acc);
    }
    red[t] = acc;
    __syncthreads();
#pragma unroll
    for (int s = 128; s; s >>= 1) {
        if (t < s) red[t] += red[t + s];
        __syncthreads();
    }
    if (!t) g_partials[blockIdx.x] = red[0];
}

// K4: final loss = (1 + BETA) * mean((z_q - z)^2)
__global__ void k_loss(float* __restrict__ lossOut) {
    __shared__ float red[256];
    const int t = threadIdx.x;
    float s = 0.f;
    for (int i = t; i < 2048; i += 256) s += g_partials[i];
    red[t] = s;
    __syncthreads();
#pragma unroll
    for (int st = 128; st; st >>= 1) {
        if (t < st) red[t] += red[t + st];
        __syncthreads();
    }
    if (!t) {
        float m = red[0] * (1.0f / 16777216.0f);
        lossOut[0] = m + 0.25f * m;
    }
}

// ---------------------------------------------------------------------------
extern "C" void kernel_launch(void* const* d_in, const int* in_sizes, int n_in,
                              void* d_out, int out_size) {
    const float* z   = (const float*)d_in[0];
    const float* emb = (const float*)d_in[1];
    float* out       = (float*)d_out;

    k_epack<<<1024, 256>>>(emb);
    k_esq<<<(KCODES * 32) / 256, 256>>>(emb);
    k_zsq<<<NROWS / 256, 256>>>(z);
    k_dist_argmin<<<NROWS / 128, 256>>>(z);
    k_output<<<NROWS / 32, 256>>>(z, emb, out);
    k_loss<<<1, 256>>>(out + (size_t)out_size - 1);
}